// round 16
// baseline (speedup 1.0000x reference)
#include <cuda_runtime.h>
#include <math.h>

// ---------------- problem constants ----------------
#define PAD_TOK 0
#define SOS_TOK 1
#define EOS_TOK 2
#define VOCAB   50000
#define EMB     512
#define HID     1024
#define OUTC    5

// ---------------- kernel geometry ----------------
#define NBLK   128
#define NTH    256
#define UNITS  8              // warp u owns unit u
#define NJX    8              // x chunks (smem weights)
#define NJH    16             // h chunks (register weights)
#define XWS_ROW 512
#define TOKCAP 2048
#define FSTR   32

typedef unsigned long long u64t;

// ---------------- global state ----------------
// h packets: {tag<<32 | h_bits}, double-buffered by step parity.
// scalar b64 relaxed accesses are single-copy atomic (proven r10).
__device__ __align__(16) u64t g_hx[2][HID];
__device__ unsigned g_flags[NBLK * FSTR];   // detection counters: +8 per step (relaxed)
__device__ unsigned g_flag2[FSTR];          // block0 -> all (emb/done), r15 release/acquire
__device__ __align__(16) float g_cur_emb[EMB];
__device__ int g_done;

// ---------------- sync primitives ----------------
__device__ __forceinline__ unsigned ld_acq(const unsigned* p) {
    unsigned v;
    asm volatile("ld.acquire.gpu.global.u32 %0, [%1];" : "=r"(v) : "l"(p) : "memory");
    return v;
}
__device__ __forceinline__ void st_rel(unsigned* p, unsigned v) {
    asm volatile("st.release.gpu.global.u32 [%0], %1;" :: "l"(p), "r"(v) : "memory");
}
__device__ __forceinline__ void wait_ge_acq(const unsigned* p, unsigned tgt) {
    while ((int)(ld_acq(p) - tgt) < 0) { }
}
// weak detection spin (counter is advisory; tags carry correctness)
__device__ __forceinline__ void wait_ge_weak(const unsigned* p, unsigned tgt) {
    unsigned v;
    do {
        asm volatile("ld.global.cg.u32 %0, [%1];" : "=r"(v) : "l"(p) : "memory");
    } while ((int)(v - tgt) < 0);
}
// fire-and-forget publish pieces
__device__ __forceinline__ void st_pkt(u64t* p, float h, unsigned tag) {
    u64t v = ((u64t)tag << 32) | (u64t)__float_as_uint(h);
    asm volatile("st.relaxed.gpu.global.b64 [%0], %1;" :: "l"(p), "l"(v) : "memory");
}
__device__ __forceinline__ u64t ld_pkt(const u64t* p) {
    u64t v;
    asm volatile("ld.relaxed.gpu.global.b64 %0, [%1];" : "=l"(v) : "l"(p) : "memory");
    return v;
}
__device__ __forceinline__ void red_add1_relaxed(unsigned* p) {
    asm volatile("red.relaxed.gpu.global.add.u32 [%0], %1;" :: "l"(p), "r"(1u) : "memory");
}

// ---------------- packed dual-FMA ----------------
__device__ __forceinline__ void fma2(u64t& d, u64t a, u64t b) {
    asm("fma.rn.f32x2 %0, %1, %2, %0;" : "+l"(d) : "l"(a), "l"(b));
}
__device__ __forceinline__ float f2lo(u64t v) { return __uint_as_float((unsigned)v); }
__device__ __forceinline__ float f2hi(u64t v) { return __uint_as_float((unsigned)(v >> 32)); }

__device__ __forceinline__ float fsig(float x)  { return __fdividef(1.0f, 1.0f + __expf(-x)); }
__device__ __forceinline__ float ftanh(float x) { return 1.0f - __fdividef(2.0f, __expf(2.0f * x) + 1.0f); }

// ---------------- smem plan ----------------
struct SM {
    float hbuf[2][HID];
    float xbuf[3][EMB];
    float xws[32 * XWS_ROW];
    int   x_tok[TOKCAP];
    float pred[OUTC];
    int   nid;
    int   done;
    unsigned sbase;
};

// ---------------- weight load (r15 verbatim) ----------------
__device__ __forceinline__ void load_w(
    const float* __restrict__ Wih, const float* __restrict__ Whh,
    const float* __restrict__ bih, const float* __restrict__ bhh,
    u64t (&wr)[4][NJH], float* xws, float (&bias)[4],
    int b, int u, int lane, int tid)
{
#pragma unroll
    for (int q = 0; q < 4; q++) {
        size_t G = (size_t)q * HID + (size_t)b * UNITS + u;
        const float* rh = Whh + G * HID;
#pragma unroll
        for (int j = 0; j < NJH; j++)
            wr[q][j] = *(const u64t*)(rh + j * 64 + lane * 2);
    }
    for (int i = tid; i < 32 * (XWS_ROW / 4); i += NTH) {
        int r = i >> 7, c = i & 127;
        int q = r >> 3, uu = r & 7;
        size_t G = (size_t)q * HID + (size_t)b * UNITS + uu;
        ((float4*)(xws + (size_t)r * XWS_ROW))[c] = ((const float4*)(Wih + G * EMB))[c];
    }
#pragma unroll
    for (int q = 0; q < 4; q++) {
        size_t G = (size_t)q * HID + (size_t)b * UNITS + u;
        bias[q] = bih[G] + bhh[G];
    }
}

__device__ __forceinline__ void mac_x(const float* xws, const float* xv,
                                      int u, int lane, u64t (&acc)[4])
{
#pragma unroll
    for (int j = 0; j < NJX; j++) {
        u64t v = *(const u64t*)(xv + j * 64 + lane * 2);
#pragma unroll
        for (int q = 0; q < 4; q++) {
            u64t wv = *(const u64t*)(xws + (size_t)(q * 8 + u) * XWS_ROW
                                         + j * 64 + lane * 2);
            fma2(acc[q], wv, v);
        }
    }
}

__device__ __forceinline__ void mac_h(const u64t (&wr)[4][NJH], const float* hv,
                                      int lane, u64t (&acc)[4])
{
#pragma unroll
    for (int j = 0; j < NJH; j++) {
        u64t v = *(const u64t*)(hv + j * 64 + lane * 2);
        fma2(acc[0], wr[0][j], v);
        fma2(acc[1], wr[1][j], v);
        fma2(acc[2], wr[2][j], v);
        fma2(acc[3], wr[3][j], v);
    }
}

// distributed finish (validated r12/r14/r15)
__device__ __forceinline__ float finish_unit(u64t (&acc)[4], const float (&bias)[4],
                                             int lane, float& cstate)
{
    float a0 = f2lo(acc[0]) + f2hi(acc[0]);
    float a1 = f2lo(acc[1]) + f2hi(acc[1]);
    float a2 = f2lo(acc[2]) + f2hi(acc[2]);
    float a3 = f2lo(acc[3]) + f2hi(acc[3]);
#pragma unroll
    for (int off = 16; off >= 4; off >>= 1) {
        a0 += __shfl_xor_sync(0xffffffffu, a0, off);
        a1 += __shfl_xor_sync(0xffffffffu, a1, off);
        a2 += __shfl_xor_sync(0xffffffffu, a2, off);
        a3 += __shfl_xor_sync(0xffffffffu, a3, off);
    }
    float t02 = (lane & 2) ? a2 : a0;
    float o02 = (lane & 2) ? a0 : a2;
    t02 += __shfl_xor_sync(0xffffffffu, o02, 2);
    float t13 = (lane & 2) ? a3 : a1;
    float o13 = (lane & 2) ? a1 : a3;
    t13 += __shfl_xor_sync(0xffffffffu, o13, 2);
    float v = (lane & 1) ? t13 : t02;
    float o = (lane & 1) ? t02 : t13;
    v += __shfl_xor_sync(0xffffffffu, o, 1);

    float bsel = (lane & 2) ? ((lane & 1) ? bias[3] : bias[2])
                            : ((lane & 1) ? bias[1] : bias[0]);
    float g = v + bsel;
    bool is_g = ((lane & 3) == 2);
    float m = is_g ? 2.0f : 1.0f;
    float c0 = is_g ? -1.0f : 0.0f;
    float act = fmaf(m, fsig(m * g), c0);

    float si = act;
    float sf = __shfl_sync(0xffffffffu, act, 1);
    float tg = __shfl_sync(0xffffffffu, act, 2);
    float so = __shfl_sync(0xffffffffu, act, 3);
    float hn = 0.0f;
    if (lane == 0) {
        float cn = sf * cstate + si * tg;
        hn = so * ftanh(cn);
        cstate = cn;
    }
    return hn;
}

// stage 8 tag-validated packets of one CTA into hbuf (batch load, batch retry)
__device__ __forceinline__ void stage_h(int par, unsigned want, float* hbuf, int tid)
{
    const u64t* pp = &g_hx[par][tid * UNITS];
    u64t p0, p1, p2, p3, p4, p5, p6, p7;
    for (;;) {
        p0 = ld_pkt(pp + 0); p1 = ld_pkt(pp + 1);
        p2 = ld_pkt(pp + 2); p3 = ld_pkt(pp + 3);
        p4 = ld_pkt(pp + 4); p5 = ld_pkt(pp + 5);
        p6 = ld_pkt(pp + 6); p7 = ld_pkt(pp + 7);
        unsigned mn = min(min(min((unsigned)(p0 >> 32), (unsigned)(p1 >> 32)),
                              min((unsigned)(p2 >> 32), (unsigned)(p3 >> 32))),
                          min(min((unsigned)(p4 >> 32), (unsigned)(p5 >> 32)),
                              min((unsigned)(p6 >> 32), (unsigned)(p7 >> 32))));
        if ((int)(mn - want) >= 0) break;
    }
    ((float4*)hbuf)[tid * 2 + 0] = make_float4(
        __uint_as_float((unsigned)p0), __uint_as_float((unsigned)p1),
        __uint_as_float((unsigned)p2), __uint_as_float((unsigned)p3));
    ((float4*)hbuf)[tid * 2 + 1] = make_float4(
        __uint_as_float((unsigned)p4), __uint_as_float((unsigned)p5),
        __uint_as_float((unsigned)p6), __uint_as_float((unsigned)p7));
}

extern __shared__ __align__(16) unsigned char smem_raw[];

__global__ void __launch_bounds__(NTH, 1)
seq2seq_kernel(const int* __restrict__ x_ids, int seq,
               const float* __restrict__ emb,
               const float* __restrict__ eWih, const float* __restrict__ eWhh,
               const float* __restrict__ ebih, const float* __restrict__ ebhh,
               const float* __restrict__ dWih, const float* __restrict__ dWhh,
               const float* __restrict__ dbih, const float* __restrict__ dbhh,
               const float* __restrict__ outW, const float* __restrict__ outb,
               const int* __restrict__ maxlen_p,
               float* __restrict__ out, int out_size)
{
    SM* s = (SM*)smem_raw;
    const int tid = threadIdx.x;
    const int b = blockIdx.x;
    const int warp = tid >> 5, lane = tid & 31;   // warp == unit u
    const int tid2 = tid - 128;

    if (tid == 0) s->sbase = __ldcg(&g_flags[b * FSTR]);   // own counter only

    u64t wr[4][NJH];
    float bias[4];
    load_w(eWih, eWhh, ebih, ebhh, wr, s->xws, bias, b, warp, lane, tid);
    float cstate = 0.0f;
    for (int k = tid; k < seq && k < TOKCAP; k += NTH) s->x_tok[k] = x_ids[k];
    __syncthreads();
    const unsigned B  = s->sbase;        // multiple of 8
    const unsigned S0 = B >> 3;          // step base; h_k carries tag S0+1+k

    // publish h_0 = 0 (packet + relaxed increment -> counter B+8)
    if (lane == 0) {
        st_pkt(&g_hx[0][b * UNITS + warp], 0.0f, S0 + 1);
        red_add1_relaxed(&g_flags[b * FSTR]);
    }
    if (b == 0) {                        // decoder feedback init + flag2 (r15 schema)
        for (int k = tid; k < out_size; k += NTH) out[k] = 0.0f;
        if (tid < EMB / 4)
            __stcg(((float4*)g_cur_emb) + tid,
                   ((const float4*)(emb + (size_t)SOS_TOK * EMB))[tid]);
        if (tid == 0) g_done = 0;
        __syncthreads();
        if (tid == 0) st_rel(&g_flag2[0], S0 + 1 + (unsigned)seq);
    }

    // bootstrap x staging
    float4 epf = make_float4(0.f, 0.f, 0.f, 0.f);
    if (tid2 >= 0 && seq > 0) {
        int tok0 = s->x_tok[0];
        ((float4*)s->xbuf[0])[tid2] = ((const float4*)(emb + (size_t)tok0 * EMB))[tid2];
        if (seq > 1) {
            int tok1 = s->x_tok[1];
            epf = ((const float4*)(emb + (size_t)tok1 * EMB))[tid2];
        }
    }
    __syncthreads();

    // ---- encoder: one sync per step; fire-and-forget publishes ----
    for (int t = 0; t < seq; t++) {
        u64t acc[4] = {0ull, 0ull, 0ull, 0ull};
        mac_x(s->xws, s->xbuf[t % 3], warp, lane, acc);

        if (tid < 128) {
            wait_ge_weak(&g_flags[tid * FSTR], B + 8u * (unsigned)(t + 1));
            stage_h(t & 1, S0 + 1u + (unsigned)t, s->hbuf[t & 1], tid);
        } else {
            if (t + 1 < seq) ((float4*)s->xbuf[(t + 1) % 3])[tid2] = epf;
            if (t + 2 < seq) {
                int tk = s->x_tok[t + 2];
                epf = ((const float4*)(emb + (size_t)tk * EMB))[tid2];
            }
        }
        __syncthreads();

        mac_h(wr, s->hbuf[t & 1], lane, acc);
        float hn = finish_unit(acc, bias, lane, cstate);
        if (lane == 0) {                 // packet + relaxed increment, no serialization
            st_pkt(&g_hx[(t + 1) & 1][b * UNITS + warp], hn, S0 + 2u + (unsigned)t);
            red_add1_relaxed(&g_flags[b * FSTR]);
        }
    }

    // ---- decoder weights ----
    __syncthreads();
    load_w(dWih, dWhh, dbih, dbhh, wr, s->xws, bias, b, warp, lane, tid);
    const int maxlen = *maxlen_p;
    __syncthreads();

    // ---- decoder: r15 structure, packet h exchange ----
    for (int d = 0; d < maxlen; d++) {
        if (tid == 0) {
            wait_ge_acq(&g_flag2[0], S0 + 1u + (unsigned)seq + (unsigned)d);
            s->done = __ldcg(&g_done);
        }
        __syncthreads();
        if (s->done) break;

        int p = (seq + d) & 1;
        if (tid < 128) {
            ((float4*)s->xbuf[0])[tid] = __ldcg(((const float4*)g_cur_emb) + tid);
            wait_ge_weak(&g_flags[tid * FSTR], B + 8u * (unsigned)(seq + d + 1));
            stage_h(p, S0 + 1u + (unsigned)(seq + d), s->hbuf[0], tid);
        }
        __syncthreads();

        u64t acc[4] = {0ull, 0ull, 0ull, 0ull};
        mac_x(s->xws, s->xbuf[0], warp, lane, acc);
        mac_h(wr, s->hbuf[0], lane, acc);
        float hn = finish_unit(acc, bias, lane, cstate);
        if (lane == 0) {
            st_pkt(&g_hx[p ^ 1][b * UNITS + warp], hn, S0 + 2u + (unsigned)(seq + d));
            red_add1_relaxed(&g_flags[b * FSTR]);
        }

        if (b == 0) {   // projection from tag-validated packets + greedy feedback
            if (tid < 128)
                wait_ge_weak(&g_flags[tid * FSTR], B + 8u * (unsigned)(seq + d + 2));
            __syncthreads();
            if (warp < OUTC) {
                const u64t* hrow = g_hx[p ^ 1];
                const unsigned want2 = S0 + 2u + (unsigned)(seq + d);
                float a = 0.0f;
                for (int k = lane; k < HID; k += 32) {
                    u64t pk;
                    do { pk = ld_pkt(&hrow[k]); }
                    while ((int)((unsigned)(pk >> 32) - want2) < 0);
                    a += __uint_as_float((unsigned)pk) * outW[(size_t)warp * HID + k];
                }
#pragma unroll
                for (int off = 16; off; off >>= 1)
                    a += __shfl_xor_sync(0xffffffffu, a, off);
                if (lane == 0) s->pred[warp] = a + outb[warp];
            }
            __syncthreads();
            if (tid == 0) {
                for (int o = 0; o < OUTC; o++) out[d * OUTC + o] = s->pred[o];
                if (maxlen * OUTC + d < out_size) out[maxlen * OUTC + d] = 1.0f;
                float r = rintf(s->pred[0]);         // half-to-even like jnp.round
                r = fminf(fmaxf(r, 0.0f), (float)(VOCAB - 1));
                int nid = (int)r;
                s->nid = nid;
                if (nid == EOS_TOK) g_done = 1;
            }
            __syncthreads();
            int nid = s->nid;
            float sc = (nid != PAD_TOK) ? 1.0f : 0.0f;
            for (int k = tid; k < EMB; k += NTH)
                __stcg(&g_cur_emb[k], emb[(size_t)nid * EMB + k] * sc);
            __syncthreads();
            if (tid == 0) st_rel(&g_flag2[0], S0 + 2u + (unsigned)seq + (unsigned)d);
        }
        __syncthreads();   // decoder buffer (hbuf[0]/xbuf[0]) reuse gate
    }
}

extern "C" void kernel_launch(void* const* d_in, const int* in_sizes, int n_in,
                              void* d_out, int out_size)
{
    const int*   x    = (const int*)  d_in[0];
    const float* emb  = (const float*)d_in[1];
    const float* eWih = (const float*)d_in[2];
    const float* eWhh = (const float*)d_in[3];
    const float* ebih = (const float*)d_in[4];
    const float* ebhh = (const float*)d_in[5];
    const float* dWih = (const float*)d_in[6];
    const float* dWhh = (const float*)d_in[7];
    const float* dbih = (const float*)d_in[8];
    const float* dbhh = (const float*)d_in[9];
    const float* outW = (const float*)d_in[10];
    const float* outb = (const float*)d_in[11];
    const int*   mlp  = (const int*)  d_in[12];
    int seq = in_sizes[0];
    if (seq > TOKCAP) seq = TOKCAP;

    int smem_bytes = (int)sizeof(SM);
    cudaFuncSetAttribute(seq2seq_kernel,
                         cudaFuncAttributeMaxDynamicSharedMemorySize, smem_bytes);
    seq2seq_kernel<<<NBLK, NTH, smem_bytes>>>(
        x, seq, emb, eWih, eWhh, ebih, ebhh,
        dWih, dWhh, dbih, dbhh, outW, outb, mlp,
        (float*)d_out, out_size);
}